// round 7
// baseline (speedup 1.0000x reference)
#include <cuda_runtime.h>
#include <cuda_bf16.h>

#define SS   8
#define HH   544
#define WW   960
#define HID  64
#define BT   256
#define FULL 0xffffffffu

__global__ __launch_bounds__(BT)
void sky_kernel(const float* __restrict__ images,
                const float* __restrict__ extr,
                const float* __restrict__ intr,
                const float* __restrict__ W1,
                const float* __restrict__ b1,
                const float* __restrict__ W2,
                const float* __restrict__ b2,
                const float* __restrict__ pcd,
                const float* __restrict__ lsc,
                const int*   __restrict__ dsp,
                float* __restrict__ out, int N, int NW, int PERM)
{
    __shared__ float sE[SS * 12];
    __shared__ float sK[SS * 9];
    __shared__ float sW1[3 * HID];
    __shared__ float sB1[HID];
    __shared__ float sW2[HID * 3];
    __shared__ float sB2[3];

    const int tid  = threadIdx.x;
    const int lane = tid & 31;

    float ds;
    {
        int iv = *dsp;
        ds = (iv > 0 && iv < 1000000) ? (float)iv : __int_as_float(iv);
    }

    if (tid < SS * 12) sE[tid] = extr[(tid / 12) * 16 + (tid % 12)];
    if (tid < SS * 9) {
        int ij = tid % 9, i = ij / 3, j = ij % 3;
        float d = 1.0f;
        if (i == 0 && (j == 0 || j == 2)) d = ds;
        if (i == 1 && (j == 1 || j == 2)) d = ds;
        sK[tid] = intr[tid] / d;
    }
    if (tid < 3 * HID) sW1[tid] = W1[tid];
    if (tid < HID)     sB1[tid] = b1[tid];
    if (tid < HID * 3) sW2[tid] = W2[(tid / 3) * 6 + (tid % 3)];
    if (tid < 3)       sB2[tid] = b2[tid];
    __syncthreads();

    // warp-granularity scatter (load balance across SMs); warp-uniform exit
    const int gwarp = (blockIdx.x * BT + tid) >> 5;
    if (gwarp >= NW) return;
    const long long pw = ((long long)gwarp * PERM) % NW;
    const int n = (int)(pw << 5) + lane;
    const bool pvalid = (n < N);

    float X = 0.f, Y = 0.f, Z = 0.f;
    if (pvalid) {
        X = pcd[3 * n + 0];
        Y = pcd[3 * n + 1];
        Z = pcd[3 * n + 2];
    }

    // ---- Phase A: visibility mask (every lane, own point) ----
    int mask = 0;
    if (pvalid) {
        #pragma unroll
        for (int s = 0; s < SS; ++s) {
            const float* E = sE + s * 12;
            const float* K = sK + s * 9;
            float c0 = E[0] * X + E[1]  * Y + E[2]  * Z + E[3];
            float c1 = E[4] * X + E[5]  * Y + E[6]  * Z + E[7];
            float c2 = E[8] * X + E[9]  * Y + E[10] * Z + E[11];
            float u = K[0] * c0 + K[1] * c1 + K[2] * c2;
            float v = K[3] * c0 + K[4] * c1 + K[5] * c2;
            float w = K[6] * c0 + K[7] * c1 + K[8] * c2;
            float zs = (fabsf(w) > 1e-6f) ? w : 1e-6f;
            float px = u / zs;
            float py = v / zs;
            bool m = (w > 0.001f) && (px >= 0.f) && (px <= (float)(WW - 1)) &&
                     (py >= 0.f) && (py <= (float)(HH - 1));
            if (m) mask |= (1 << s);
        }
    }

    const unsigned visBits = __ballot_sync(FULL, mask != 0);
    const int V       = __popc(visBits);
    const int p_rank  = __popc(visBits & ((1u << lane) - 1u));  // rank among visible
    const bool visown = (mask != 0);

    float f0 = 0.f, f1 = 0.f, f2 = 0.f;

    // ---- Phase B: cooperative bilinear over (point, cam) pairs ----
    const int nPairRounds = (V * 8 + 31) >> 5;
    for (int w = 0; w < nPairRounds; ++w) {
        const int pairIdx = (w << 5) + lane;
        const int p_sel   = pairIdx >> 3;
        const int cam     = pairIdx & 7;
        const bool pin    = (p_sel < V);
        const int src     = pin ? __fns(visBits, 0, p_sel + 1) : 0;

        const float Xp = __shfl_sync(FULL, X, src);
        const float Yp = __shfl_sync(FULL, Y, src);
        const float Zp = __shfl_sync(FULL, Z, src);
        const int   mp = __shfl_sync(FULL, mask, src);

        float r0 = 0.f, r1 = 0.f, r2 = 0.f;
        if (pin && ((mp >> cam) & 1)) {
            const float* E = sE + cam * 12;
            const float* K = sK + cam * 9;
            float c0 = E[0] * Xp + E[1]  * Yp + E[2]  * Zp + E[3];
            float c1 = E[4] * Xp + E[5]  * Yp + E[6]  * Zp + E[7];
            float c2 = E[8] * Xp + E[9]  * Yp + E[10] * Zp + E[11];
            float u = K[0] * c0 + K[1] * c1 + K[2] * c2;
            float v = K[3] * c0 + K[4] * c1 + K[5] * c2;
            float wz = K[6] * c0 + K[7] * c1 + K[8] * c2;
            float zs = (fabsf(wz) > 1e-6f) ? wz : 1e-6f;
            float px = u / zs;
            float py = v / zs;
            int x0 = (int)floorf(px); x0 = min(max(x0, 0), WW - 2);
            int y0 = (int)floorf(py); y0 = min(max(y0, 0), HH - 2);
            float wx = px - (float)x0;
            float wy = py - (float)y0;
            float w00 = (1.f - wx) * (1.f - wy);
            float w01 = wx * (1.f - wy);
            float w10 = (1.f - wx) * wy;
            float w11 = wx * wy;
            const float* img = images + (size_t)cam * 3 * HH * WW + (size_t)y0 * WW + x0;
            const float* pA = img;
            const float* pB = img + (size_t)HH * WW;
            const float* pC = img + (size_t)2 * HH * WW;
            float a00 = __ldg(pA),      a01 = __ldg(pA + 1);
            float a10 = __ldg(pA + WW), a11 = __ldg(pA + WW + 1);
            float e00 = __ldg(pB),      e01 = __ldg(pB + 1);
            float e10 = __ldg(pB + WW), e11 = __ldg(pB + WW + 1);
            float g00 = __ldg(pC),      g01 = __ldg(pC + 1);
            float g10 = __ldg(pC + WW), g11 = __ldg(pC + WW + 1);
            r0 = a00 * w00 + a01 * w01 + a10 * w10 + a11 * w11;
            r1 = e00 * w00 + e01 * w01 + e10 * w10 + e11 * w11;
            r2 = g00 * w00 + g01 * w01 + g10 * w10 + g11 * w11;
        }

        // 8-lane (camera) tree reduce; leader = lane 0 of each group of 8
        #pragma unroll
        for (int d = 4; d; d >>= 1) {
            r0 += __shfl_down_sync(FULL, r0, d);
            r1 += __shfl_down_sync(FULL, r1, d);
            r2 += __shfl_down_sync(FULL, r2, d);
        }

        // owners of points handled this round collect from group leaders
        const int leader = (p_rank & 3) << 3;
        const float q0 = __shfl_sync(FULL, r0, leader);
        const float q1 = __shfl_sync(FULL, r1, leader);
        const float q2 = __shfl_sync(FULL, r2, leader);
        if (visown && ((p_rank >> 2) == w)) { f0 = q0; f1 = q1; f2 = q2; }
    }

    // normalize by count (owner-local)
    if (visown) {
        const float inv = 1.f / (float)__popc(mask);
        f0 *= inv; f1 *= inv; f2 *= inv;
    }

    // ---- Phase C: cooperative MLP (8 lanes x 8 hidden units per point) ----
    float a0 = 0.f, a1 = 0.f, a2 = 0.f;
    const int nMlpRounds = (V + 3) >> 2;
    for (int w = 0; w < nMlpRounds; ++w) {
        const int p_sel = (w << 2) + (lane >> 3);
        const bool pin  = (p_sel < V);
        const int src   = pin ? __fns(visBits, 0, p_sel + 1) : 0;
        const float g0 = __shfl_sync(FULL, f0, src);
        const float g1 = __shfl_sync(FULL, f1, src);
        const float g2 = __shfl_sync(FULL, f2, src);

        float b0 = 0.f, b1_ = 0.f, b2_ = 0.f;
        if (pin) {
            const int jb = (lane & 7) << 3;
            #pragma unroll
            for (int jj = 0; jj < 8; ++jj) {
                const int j = jb + jj;
                float h = g0 * sW1[j] + g1 * sW1[HID + j] + g2 * sW1[2 * HID + j] + sB1[j];
                h = fmaxf(h, 0.f);
                b0  = fmaf(h, sW2[j * 3 + 0], b0);
                b1_ = fmaf(h, sW2[j * 3 + 1], b1_);
                b2_ = fmaf(h, sW2[j * 3 + 2], b2_);
            }
        }
        #pragma unroll
        for (int d = 4; d; d >>= 1) {
            b0  += __shfl_down_sync(FULL, b0, d);
            b1_ += __shfl_down_sync(FULL, b1_, d);
            b2_ += __shfl_down_sync(FULL, b2_, d);
        }
        const int leader = (p_rank & 3) << 3;
        const float q0 = __shfl_sync(FULL, b0, leader);
        const float q1 = __shfl_sync(FULL, b1_, leader);
        const float q2 = __shfl_sync(FULL, b2_, leader);
        if (visown && ((p_rank >> 2) == w)) {
            a0 = q0 + sB2[0]; a1 = q1 + sB2[1]; a2 = q2 + sB2[2];
        }
    }

    // ---- Output ----
    if (!pvalid) return;
    float2* op = (float2*)(out + (size_t)6 * n);
    if (!visown) {
        op[0] = make_float2(0.f, 0.f);
        op[1] = make_float2(0.f, 0.f);
        op[2] = make_float2(0.f, 0.f);
    } else {
        op[0] = make_float2(tanhf(a0), tanhf(a1));
        op[1] = make_float2(tanhf(a2), __expf(lsc[3 * n + 0]));
        op[2] = make_float2(__expf(lsc[3 * n + 1]), __expf(lsc[3 * n + 2]));
    }
}

extern "C" void kernel_launch(void* const* d_in, const int* in_sizes, int n_in,
                              void* d_out, int out_size)
{
    const float* images = (const float*)d_in[0];
    const float* extr   = (const float*)d_in[1];
    const float* intr   = (const float*)d_in[2];
    const float* W1     = (const float*)d_in[3];
    const float* b1     = (const float*)d_in[4];
    const float* W2     = (const float*)d_in[5];
    const float* b2     = (const float*)d_in[6];
    const float* pcd    = (const float*)d_in[7];
    const float* lsc    = (const float*)d_in[8];
    const int*   dsp    = (const int*)  d_in[9];

    int N  = in_sizes[7] / 3;
    int NW = (N + 31) / 32;

    int PERM = (int)(0.6180339887 * NW) | 1;
    while (true) {
        int a = PERM, b = NW;
        while (b) { int t = a % b; a = b; b = t; }
        if (a == 1) break;
        PERM += 2;
    }

    int blocks = (NW * 32 + BT - 1) / BT;
    sky_kernel<<<blocks, BT>>>(images, extr, intr, W1, b1, W2, b2,
                               pcd, lsc, dsp, (float*)d_out, N, NW, PERM);
}